// round 8
// baseline (speedup 1.0000x reference)
#include <cuda_runtime.h>
#include <cuda_fp16.h>

#define NN   100000
#define EE   1600000
#define DIN  128
#define DHID 64
#define DOUT 16
#define NB1  ((NN + 1023) / 1024)   // 98 scan blocks

// Scratch (__device__ globals; allocation-free rule).
__device__ float g_dinv[NN];
__device__ __align__(16) __half g_hs1h[NN * DHID];   // raw xW1, fp16
__device__ float g_hs2[NN * DOUT];
__device__ int   g_cnt[NN];
__device__ int   g_offx[NN];
__device__ int   g_cur[NN];
__device__ int   g_esrc[EE];
__device__ unsigned long long g_state[NB1];   // lookback: (flag<<32)|value

__device__ __forceinline__ unsigned h2u(__half2 h) {
    return *reinterpret_cast<unsigned*>(&h);
}

// ---------------------------------------------------------------------------
__global__ void k_zero() {
    int i = blockIdx.x * blockDim.x + threadIdx.x;
    if (i < NN)  g_cnt[i]   = 0;
    if (i < NB1) g_state[i] = 0ULL;
}

__global__ void k_count(const int* __restrict__ dst) {
    int e = blockIdx.x * blockDim.x + threadIdx.x;
    if (e < EE) atomicAdd(&g_cnt[dst[e]], 1);
}

// Single-pass scan with decoupled lookback. flag: 0=invalid 1=aggregate 2=prefix.
__global__ __launch_bounds__(1024) void k_scanL() {
    __shared__ int ws[32];
    __shared__ int s_excl;
    int bid = blockIdx.x;
    int i = bid * 1024 + threadIdx.x;
    int lane = threadIdx.x & 31, wid = threadIdx.x >> 5;

    int v = (i < NN) ? g_cnt[i] : 0;
    int s = v;
    #pragma unroll
    for (int d = 1; d < 32; d <<= 1) {
        int t = __shfl_up_sync(0xffffffff, s, d);
        if (lane >= d) s += t;
    }
    if (lane == 31) ws[wid] = s;
    __syncthreads();
    if (wid == 0) {
        int w = ws[lane];
        #pragma unroll
        for (int d = 1; d < 32; d <<= 1) {
            int t = __shfl_up_sync(0xffffffff, w, d);
            if (lane >= d) w += t;
        }
        ws[lane] = w;
    }
    __syncthreads();

    if (threadIdx.x == 0) {
        int total = ws[31];
        if (bid == 0) {
            atomicExch(&g_state[0], (2ULL << 32) | (unsigned)total);
            s_excl = 0;
        } else {
            atomicExch(&g_state[bid], (1ULL << 32) | (unsigned)total);
            int excl = 0, p = bid - 1;
            while (true) {
                unsigned long long st;
                do { st = atomicAdd(&g_state[p], 0ULL); } while ((st >> 32) == 0);
                excl += (int)(unsigned)st;
                if ((st >> 32) == 2ULL) break;
                p--;
            }
            atomicExch(&g_state[bid], (2ULL << 32) | (unsigned)(excl + total));
            s_excl = excl;
        }
    }
    __syncthreads();

    if (i < NN) {
        int inclB = s + (wid > 0 ? ws[wid - 1] : 0);   // block-local inclusive
        int excl  = s_excl + inclB - v;
        g_offx[i] = excl;
        g_cur[i]  = excl;
        g_dinv[i] = rsqrtf((float)(v + 1));
    }
}

__global__ void k_fill(const int* __restrict__ src, const int* __restrict__ dst) {
    int e = blockIdx.x * blockDim.x + threadIdx.x;
    if (e >= EE) return;
    int d = dst[e];
    int p = atomicAdd(&g_cur[d], 1);
    g_esrc[p] = src[e];
}

// ---------------------------------------------------------------------------
// GEMM1 on tensor cores (fp16 HMMA, fp32 accum): hs1h = x @ W1.
#define XS_STRIDE 136
#define WS_STRIDE 72
#define GEMM1_SMEM ((256 * XS_STRIDE + DIN * WS_STRIDE) * 2)

__device__ __forceinline__ void ldsm_x4(unsigned* d, unsigned addr) {
    asm volatile("ldmatrix.sync.aligned.m8n8.x4.shared.b16 {%0,%1,%2,%3}, [%4];"
        : "=r"(d[0]), "=r"(d[1]), "=r"(d[2]), "=r"(d[3]) : "r"(addr));
}
__device__ __forceinline__ void ldsm_x4_t(unsigned* d, unsigned addr) {
    asm volatile("ldmatrix.sync.aligned.m8n8.x4.trans.shared.b16 {%0,%1,%2,%3}, [%4];"
        : "=r"(d[0]), "=r"(d[1]), "=r"(d[2]), "=r"(d[3]) : "r"(addr));
}
__device__ __forceinline__ void mma16816(float* c, const unsigned* a,
                                         unsigned b0, unsigned b1) {
    asm volatile("mma.sync.aligned.m16n8k16.row.col.f32.f16.f16.f32 "
        "{%0,%1,%2,%3}, {%4,%5,%6,%7}, {%8,%9}, {%0,%1,%2,%3};"
        : "+f"(c[0]), "+f"(c[1]), "+f"(c[2]), "+f"(c[3])
        : "r"(a[0]), "r"(a[1]), "r"(a[2]), "r"(a[3]), "r"(b0), "r"(b1));
}

__global__ __launch_bounds__(256) void k_gemm1(const float* __restrict__ x,
                                               const float* __restrict__ W1) {
    extern __shared__ __half sm[];
    __half* xs = sm;                        // [256][XS_STRIDE]
    __half* ws = sm + 256 * XS_STRIDE;      // [128][WS_STRIDE]
    int tid = threadIdx.x;
    int rowBase = blockIdx.x * 256;

    for (int i = tid; i < DIN * DHID; i += 256) {
        int k = i >> 6, n = i & 63;
        ws[k * WS_STRIDE + n] = __float2half(W1[i]);
    }
    const float4* x4 = (const float4*)x;
    #pragma unroll
    for (int it = 0; it < 32; it++) {
        int f   = tid + it * 256;
        int row = f >> 5, c4 = f & 31;
        if (rowBase + row < NN) {
            float4 v = x4[(long)(rowBase + row) * 32 + c4];
            uint2 u;
            u.x = h2u(__floats2half2_rn(v.x, v.y));
            u.y = h2u(__floats2half2_rn(v.z, v.w));
            *reinterpret_cast<uint2*>(&xs[row * XS_STRIDE + c4 * 4]) = u;
        }
    }
    __syncthreads();

    int warp = tid >> 5, lane = tid & 31;
    int g = lane >> 3, r = lane & 7;

    float c[2][8][4];
    #pragma unroll
    for (int mt = 0; mt < 2; mt++)
        #pragma unroll
        for (int nt = 0; nt < 8; nt++)
            #pragma unroll
            for (int q = 0; q < 4; q++) c[mt][nt][q] = 0.f;

    unsigned xs_base = (unsigned)__cvta_generic_to_shared(xs);
    unsigned ws_base = (unsigned)__cvta_generic_to_shared(ws);

    #pragma unroll
    for (int kk = 0; kk < 8; kk++) {
        unsigned a[2][4];
        #pragma unroll
        for (int mt = 0; mt < 2; mt++) {
            int m = warp * 32 + mt * 16 + (g & 1) * 8 + r;
            unsigned addr = xs_base + (m * XS_STRIDE + kk * 16 + (g >> 1) * 8) * 2;
            ldsm_x4(a[mt], addr);
        }
        #pragma unroll
        for (int np = 0; np < 4; np++) {
            int k = kk * 16 + (g & 1) * 8 + r;
            int n = np * 16 + (g >> 1) * 8;
            unsigned addr = ws_base + (k * WS_STRIDE + n) * 2;
            unsigned b[4];
            ldsm_x4_t(b, addr);
            mma16816(c[0][np * 2 + 0], a[0], b[0], b[1]);
            mma16816(c[0][np * 2 + 1], a[0], b[2], b[3]);
            mma16816(c[1][np * 2 + 0], a[1], b[0], b[1]);
            mma16816(c[1][np * 2 + 1], a[1], b[2], b[3]);
        }
    }

    int rq = lane >> 2, cq = (lane & 3) * 2;
    #pragma unroll
    for (int mt = 0; mt < 2; mt++) {
        int row0 = rowBase + warp * 32 + mt * 16 + rq;
        #pragma unroll
        for (int nt = 0; nt < 8; nt++) {
            int col = nt * 8 + cq;
            if (row0 < NN)
                *reinterpret_cast<__half2*>(g_hs1h + (long)row0 * DHID + col) =
                    __floats2half2_rn(c[mt][nt][0], c[mt][nt][1]);
            if (row0 + 8 < NN)
                *reinterpret_cast<__half2*>(g_hs1h + (long)(row0 + 8) * DHID + col) =
                    __floats2half2_rn(c[mt][nt][2], c[mt][nt][3]);
        }
    }
}

// ---------------------------------------------------------------------------
// Fused agg1 + gemm2: one warp per node.
//  1) aggregate hs1 over in-edges (2 feats/lane) -> x1 row in registers
//  2) x1 row @ W2 (W2^T in smem, conflict-free LDS.64)
//  3) value-splitting butterfly (16 shuffles) -> lane c<16 holds hs2[n][c]
__global__ __launch_bounds__(256) void k_agg1f(const float* __restrict__ b1,
                                               const float* __restrict__ W2) {
    __shared__ float sW2t[DOUT * DHID];   // [c][k], 4 KB
    int tid = threadIdx.x;
    for (int i = tid; i < DOUT * DHID; i += 256) {
        int c = i >> 6, k = i & 63;
        sW2t[i] = W2[k * DOUT + c];
    }
    __syncthreads();

    int n    = (blockIdx.x * 256 + tid) >> 5;
    int lane = tid & 31;
    if (n >= NN) return;
    int off = g_offx[n];
    int cnt = g_cnt[n];
    float dvn = g_dinv[n];

    const __half2* hs = (const __half2*)g_hs1h;
    float2 self = __half22float2(hs[(long)n * 32 + lane]);
    float2 acc;
    acc.x = self.x * dvn;
    acc.y = self.y * dvn;

    for (int base = 0; base < cnt; base += 32) {
        int idx = base + lane;
        int   e  = 0;
        float ds = 0.f;
        if (idx < cnt) {
            e  = g_esrc[off + idx];
            ds = g_dinv[e];
        }
        int m = min(32, cnt - base);
        for (int j = 0; j < m; j++) {
            int   s  = __shfl_sync(0xffffffff, e, j);
            float dj = __shfl_sync(0xffffffff, ds, j);
            float2 v = __half22float2(hs[(long)s * 32 + lane]);
            acc.x += v.x * dj;
            acc.y += v.y * dj;
        }
    }

    float2 b = ((const float2*)b1)[lane];
    float x0 = fmaxf(dvn * acc.x + b.x, 0.f);
    float x1 = fmaxf(dvn * acc.y + b.y, 0.f);

    // partial products: p[c] = x0*W2[2*lane][c] + x1*W2[2*lane+1][c]
    float p[16];
    #pragma unroll
    for (int c = 0; c < 16; c++) {
        float2 w = ((const float2*)&sW2t[c * DHID])[lane];
        p[c] = x0 * w.x + x1 * w.y;
    }

    // value-splitting butterfly: after stage s, each lane keeps cols whose
    // bit s equals lane bit s. Final: lane l holds col (l & 15).
    unsigned full = 0xffffffff;
    int b0 = lane & 1, b1i = (lane >> 1) & 1, b2 = (lane >> 2) & 1, b3 = (lane >> 3) & 1;
    float q8[8];
    #pragma unroll
    for (int j = 0; j < 8; j++) {
        float send = b0 ? p[2 * j] : p[2 * j + 1];
        float keep = b0 ? p[2 * j + 1] : p[2 * j];
        q8[j] = keep + __shfl_xor_sync(full, send, 1);
    }
    float q4[4];
    #pragma unroll
    for (int j = 0; j < 4; j++) {
        float send = b1i ? q8[2 * j] : q8[2 * j + 1];
        float keep = b1i ? q8[2 * j + 1] : q8[2 * j];
        q4[j] = keep + __shfl_xor_sync(full, send, 2);
    }
    float q2[2];
    #pragma unroll
    for (int j = 0; j < 2; j++) {
        float send = b2 ? q4[2 * j] : q4[2 * j + 1];
        float keep = b2 ? q4[2 * j + 1] : q4[2 * j];
        q2[j] = keep + __shfl_xor_sync(full, send, 4);
    }
    {
        float send = b3 ? q2[0] : q2[1];
        float keep = b3 ? q2[1] : q2[0];
        float r = keep + __shfl_xor_sync(full, send, 8);
        r += __shfl_xor_sync(full, r, 16);
        if (lane < 16)
            g_hs2[(long)n * DOUT + lane] = r * dvn;
    }
}

// ---------------------------------------------------------------------------
// agg2: 8-lane group per node, per-group shuffle masks (groups diverge).
__global__ __launch_bounds__(256) void k_agg2(const float* __restrict__ b2,
                                              float* __restrict__ out) {
    int grp  = (blockIdx.x * 256 + threadIdx.x) >> 3;
    int gl   = threadIdx.x & 7;
    unsigned gmask = 0xFFu << (threadIdx.x & 24);
    if (grp >= NN) return;
    int n   = grp;
    int off = g_offx[n];
    int cnt = g_cnt[n];

    const float2* hs = (const float2*)g_hs2;
    float2 acc = hs[(long)n * 8 + gl];

    for (int base = 0; base < cnt; base += 8) {
        int idx = base + gl;
        int e   = (idx < cnt) ? g_esrc[off + idx] : 0;
        int m   = min(8, cnt - base);
        for (int j = 0; j < m; j++) {
            int s = __shfl_sync(gmask, e, j, 8);
            float2 v = hs[(long)s * 8 + gl];
            acc.x += v.x;
            acc.y += v.y;
        }
    }

    float dv = g_dinv[n];
    float2 b = ((const float2*)b2)[gl];
    float vx = dv * acc.x + b.x;
    float vy = dv * acc.y + b.y;

    float m = fmaxf(vx, vy);
    #pragma unroll
    for (int d = 4; d >= 1; d >>= 1)
        m = fmaxf(m, __shfl_xor_sync(gmask, m, d, 8));
    float s = expf(vx - m) + expf(vy - m);
    #pragma unroll
    for (int d = 4; d >= 1; d >>= 1)
        s += __shfl_xor_sync(gmask, s, d, 8);
    float ls = m + logf(s);

    ((float2*)out)[(long)n * 8 + gl] = make_float2(vx - ls, vy - ls);
}

// ---------------------------------------------------------------------------
extern "C" void kernel_launch(void* const* d_in, const int* in_sizes, int n_in,
                              void* d_out, int out_size) {
    const float* x  = (const float*)d_in[0];
    const int*   ei = (const int*)  d_in[1];
    const float* W1 = (const float*)d_in[2];
    const float* b1 = (const float*)d_in[3];
    const float* W2 = (const float*)d_in[4];
    const float* b2 = (const float*)d_in[5];
    const int* src = ei;
    const int* dst = ei + EE;

    static cudaStream_t s2 = nullptr;
    static cudaEvent_t  e0 = nullptr, e1 = nullptr;
    if (!s2) {
        cudaStreamCreate(&s2);
        cudaEventCreateWithFlags(&e0, cudaEventDisableTiming);
        cudaEventCreateWithFlags(&e1, cudaEventDisableTiming);
        cudaFuncSetAttribute(k_gemm1, cudaFuncAttributeMaxDynamicSharedMemorySize,
                             GEMM1_SMEM);
    }

    // Fork: CSR build on s2, concurrent with gemm1 on the main stream.
    cudaEventRecord(e0, 0);
    cudaStreamWaitEvent(s2, e0, 0);

    k_zero  <<<(NN + 255) / 256, 256, 0, s2>>>();
    k_count <<<(EE + 255) / 256, 256, 0, s2>>>(dst);
    k_scanL <<<NB1, 1024, 0, s2>>>();
    k_fill  <<<(EE + 255) / 256, 256, 0, s2>>>(src, dst);
    cudaEventRecord(e1, s2);

    k_gemm1 <<<(NN + 255) / 256, 256, GEMM1_SMEM>>>(x, W1);

    // Join: agg1f needs both gemm1 (main) and CSR (s2).
    cudaStreamWaitEvent(0, e1, 0);

    k_agg1f <<<(NN * 32 + 255) / 256, 256>>>(b1, W2);
    k_agg2  <<<(NN * 8 + 255) / 256, 256>>>(b2, (float*)d_out);
}

// round 9
// speedup vs baseline: 1.0171x; 1.0171x over previous
#include <cuda_runtime.h>
#include <cuda_fp16.h>

#define NN   100000
#define EE   1600000
#define DIN  128
#define DHID 64
#define DOUT 16
#define NB1  ((NN + 1023) / 1024)   // 98 scan blocks

// Scratch (__device__ globals; allocation-free rule).
__device__ float g_dinv[NN];
__device__ __align__(16) __half g_hs1h[NN * DHID];   // raw xW1, fp16
__device__ float g_hs2[NN * DOUT];
__device__ int   g_cnt[NN];
__device__ int   g_offx[NN];
__device__ int   g_cur[NN];
__device__ int   g_esrc[EE];
__device__ unsigned long long g_state[NB1];   // lookback: (flag<<32)|value

__device__ __forceinline__ unsigned h2u(__half2 h) {
    return *reinterpret_cast<unsigned*>(&h);
}

// ---------------------------------------------------------------------------
__global__ void k_zero() {
    int i = blockIdx.x * blockDim.x + threadIdx.x;
    if (i < NN)  g_cnt[i]   = 0;
    if (i < NB1) g_state[i] = 0ULL;
}

__global__ void k_count(const int* __restrict__ dst) {
    int e = blockIdx.x * blockDim.x + threadIdx.x;
    if (e < EE) atomicAdd(&g_cnt[dst[e]], 1);
}

// Single-pass scan, WARP-PARALLEL decoupled lookback.
// flag: 0=invalid 1=aggregate 2=prefix.
__global__ __launch_bounds__(1024) void k_scanL() {
    __shared__ int ws[32];
    __shared__ int s_excl;
    int bid = blockIdx.x;
    int i = bid * 1024 + threadIdx.x;
    int lane = threadIdx.x & 31, wid = threadIdx.x >> 5;
    const unsigned full = 0xffffffffu;

    int v = (i < NN) ? g_cnt[i] : 0;
    int s = v;
    #pragma unroll
    for (int d = 1; d < 32; d <<= 1) {
        int t = __shfl_up_sync(full, s, d);
        if (lane >= d) s += t;
    }
    if (lane == 31) ws[wid] = s;
    __syncthreads();
    if (wid == 0) {
        int w = ws[lane];
        #pragma unroll
        for (int d = 1; d < 32; d <<= 1) {
            int t = __shfl_up_sync(full, w, d);
            if (lane >= d) w += t;
        }
        ws[lane] = w;
    }
    __syncthreads();

    // warp 0 does the lookback cooperatively
    if (wid == 0) {
        int total = ws[31];
        if (bid == 0) {
            if (lane == 0) {
                atomicExch(&g_state[0], (2ULL << 32) | (unsigned)total);
                s_excl = 0;
            }
        } else {
            if (lane == 0)
                atomicExch(&g_state[bid], (1ULL << 32) | (unsigned)total);
            int excl = 0;
            int p = bid - 1;             // window head; lane reads p - lane
            while (true) {
                int idx = p - lane;
                unsigned long long st = (idx >= 0)
                    ? atomicAdd(&g_state[idx], 0ULL)
                    : (2ULL << 32);      // synthetic prefix 0 beyond the front
                unsigned flag = (unsigned)(st >> 32);
                int      val  = (int)(unsigned)st;
                unsigned zero_mask = __ballot_sync(full, flag == 0);
                unsigned pref_mask = __ballot_sync(full, flag == 2);
                int firstPref = pref_mask ? (__ffs(pref_mask) - 1) : 32;
                unsigned before = (firstPref >= 32) ? full
                                                    : ((firstPref == 31) ? 0x7fffffffu
                                                                         : ((1u << firstPref) - 1));
                if (zero_mask & before) continue;       // gap before prefix: retry
                if (firstPref < 32) {
                    int contrib = (lane <= firstPref) ? val : 0;
                    #pragma unroll
                    for (int d = 16; d >= 1; d >>= 1)
                        contrib += __shfl_xor_sync(full, contrib, d);
                    excl += contrib;
                    break;
                } else {
                    if (zero_mask) continue;            // need all aggregates valid
                    int contrib = (idx >= 0) ? val : 0;
                    #pragma unroll
                    for (int d = 16; d >= 1; d >>= 1)
                        contrib += __shfl_xor_sync(full, contrib, d);
                    excl += contrib;
                    p -= 32;
                }
            }
            if (lane == 0) {
                atomicExch(&g_state[bid], (2ULL << 32) | (unsigned)(excl + total));
                s_excl = excl;
            }
        }
    }
    __syncthreads();

    if (i < NN) {
        int inclB = s + (wid > 0 ? ws[wid - 1] : 0);   // block-local inclusive
        int excl  = s_excl + inclB - v;
        g_offx[i] = excl;
        g_cur[i]  = excl;
        g_dinv[i] = rsqrtf((float)(v + 1));
    }
}

__global__ void k_fill(const int* __restrict__ src, const int* __restrict__ dst) {
    int e = blockIdx.x * blockDim.x + threadIdx.x;
    if (e >= EE) return;
    int d = dst[e];
    int p = atomicAdd(&g_cur[d], 1);
    g_esrc[p] = src[e];
}

// ---------------------------------------------------------------------------
// GEMM1 on tensor cores (fp16 HMMA, fp32 accum): hs1h = x @ W1.
#define XS_STRIDE 136
#define WS_STRIDE 72
#define GEMM1_SMEM ((256 * XS_STRIDE + DIN * WS_STRIDE) * 2)

__device__ __forceinline__ void ldsm_x4(unsigned* d, unsigned addr) {
    asm volatile("ldmatrix.sync.aligned.m8n8.x4.shared.b16 {%0,%1,%2,%3}, [%4];"
        : "=r"(d[0]), "=r"(d[1]), "=r"(d[2]), "=r"(d[3]) : "r"(addr));
}
__device__ __forceinline__ void ldsm_x4_t(unsigned* d, unsigned addr) {
    asm volatile("ldmatrix.sync.aligned.m8n8.x4.trans.shared.b16 {%0,%1,%2,%3}, [%4];"
        : "=r"(d[0]), "=r"(d[1]), "=r"(d[2]), "=r"(d[3]) : "r"(addr));
}
__device__ __forceinline__ void mma16816(float* c, const unsigned* a,
                                         unsigned b0, unsigned b1) {
    asm volatile("mma.sync.aligned.m16n8k16.row.col.f32.f16.f16.f32 "
        "{%0,%1,%2,%3}, {%4,%5,%6,%7}, {%8,%9}, {%0,%1,%2,%3};"
        : "+f"(c[0]), "+f"(c[1]), "+f"(c[2]), "+f"(c[3])
        : "r"(a[0]), "r"(a[1]), "r"(a[2]), "r"(a[3]), "r"(b0), "r"(b1));
}

__global__ __launch_bounds__(256) void k_gemm1(const float* __restrict__ x,
                                               const float* __restrict__ W1) {
    extern __shared__ __half sm[];
    __half* xs = sm;                        // [256][XS_STRIDE]
    __half* ws = sm + 256 * XS_STRIDE;      // [128][WS_STRIDE]
    int tid = threadIdx.x;
    int rowBase = blockIdx.x * 256;

    for (int i = tid; i < DIN * DHID; i += 256) {
        int k = i >> 6, n = i & 63;
        ws[k * WS_STRIDE + n] = __float2half(W1[i]);
    }
    const float4* x4 = (const float4*)x;
    #pragma unroll
    for (int it = 0; it < 32; it++) {
        int f   = tid + it * 256;
        int row = f >> 5, c4 = f & 31;
        if (rowBase + row < NN) {
            float4 v = x4[(long)(rowBase + row) * 32 + c4];
            uint2 u;
            u.x = h2u(__floats2half2_rn(v.x, v.y));
            u.y = h2u(__floats2half2_rn(v.z, v.w));
            *reinterpret_cast<uint2*>(&xs[row * XS_STRIDE + c4 * 4]) = u;
        }
    }
    __syncthreads();

    int warp = tid >> 5, lane = tid & 31;
    int g = lane >> 3, r = lane & 7;

    float c[2][8][4];
    #pragma unroll
    for (int mt = 0; mt < 2; mt++)
        #pragma unroll
        for (int nt = 0; nt < 8; nt++)
            #pragma unroll
            for (int q = 0; q < 4; q++) c[mt][nt][q] = 0.f;

    unsigned xs_base = (unsigned)__cvta_generic_to_shared(xs);
    unsigned ws_base = (unsigned)__cvta_generic_to_shared(ws);

    #pragma unroll
    for (int kk = 0; kk < 8; kk++) {
        unsigned a[2][4];
        #pragma unroll
        for (int mt = 0; mt < 2; mt++) {
            int m = warp * 32 + mt * 16 + (g & 1) * 8 + r;
            unsigned addr = xs_base + (m * XS_STRIDE + kk * 16 + (g >> 1) * 8) * 2;
            ldsm_x4(a[mt], addr);
        }
        #pragma unroll
        for (int np = 0; np < 4; np++) {
            int k = kk * 16 + (g & 1) * 8 + r;
            int n = np * 16 + (g >> 1) * 8;
            unsigned addr = ws_base + (k * WS_STRIDE + n) * 2;
            unsigned b[4];
            ldsm_x4_t(b, addr);
            mma16816(c[0][np * 2 + 0], a[0], b[0], b[1]);
            mma16816(c[0][np * 2 + 1], a[0], b[2], b[3]);
            mma16816(c[1][np * 2 + 0], a[1], b[0], b[1]);
            mma16816(c[1][np * 2 + 1], a[1], b[2], b[3]);
        }
    }

    int rq = lane >> 2, cq = (lane & 3) * 2;
    #pragma unroll
    for (int mt = 0; mt < 2; mt++) {
        int row0 = rowBase + warp * 32 + mt * 16 + rq;
        #pragma unroll
        for (int nt = 0; nt < 8; nt++) {
            int col = nt * 8 + cq;
            if (row0 < NN)
                *reinterpret_cast<__half2*>(g_hs1h + (long)row0 * DHID + col) =
                    __floats2half2_rn(c[mt][nt][0], c[mt][nt][1]);
            if (row0 + 8 < NN)
                *reinterpret_cast<__half2*>(g_hs1h + (long)(row0 + 8) * DHID + col) =
                    __floats2half2_rn(c[mt][nt][2], c[mt][nt][3]);
        }
    }
}

// ---------------------------------------------------------------------------
// Fused agg1 + gemm2: one warp per node.
__global__ __launch_bounds__(256) void k_agg1f(const float* __restrict__ b1,
                                               const float* __restrict__ W2) {
    __shared__ float sW2t[DOUT * DHID];   // [c][k], 4 KB
    int tid = threadIdx.x;
    for (int i = tid; i < DOUT * DHID; i += 256) {
        int c = i >> 6, k = i & 63;
        sW2t[i] = W2[k * DOUT + c];
    }
    __syncthreads();

    int n    = (blockIdx.x * 256 + tid) >> 5;
    int lane = tid & 31;
    if (n >= NN) return;
    int off = g_offx[n];
    int cnt = g_cnt[n];
    float dvn = g_dinv[n];

    const __half2* hs = (const __half2*)g_hs1h;
    float2 self = __half22float2(hs[(long)n * 32 + lane]);
    float2 acc;
    acc.x = self.x * dvn;
    acc.y = self.y * dvn;

    for (int base = 0; base < cnt; base += 32) {
        int idx = base + lane;
        int   e  = 0;
        float ds = 0.f;
        if (idx < cnt) {
            e  = g_esrc[off + idx];
            ds = g_dinv[e];
        }
        int m = min(32, cnt - base);
        for (int j = 0; j < m; j++) {
            int   s  = __shfl_sync(0xffffffff, e, j);
            float dj = __shfl_sync(0xffffffff, ds, j);
            float2 v = __half22float2(hs[(long)s * 32 + lane]);
            acc.x += v.x * dj;
            acc.y += v.y * dj;
        }
    }

    float2 b = ((const float2*)b1)[lane];
    float x0 = fmaxf(dvn * acc.x + b.x, 0.f);
    float x1 = fmaxf(dvn * acc.y + b.y, 0.f);

    float p[16];
    #pragma unroll
    for (int c = 0; c < 16; c++) {
        float2 w = ((const float2*)&sW2t[c * DHID])[lane];
        p[c] = x0 * w.x + x1 * w.y;
    }

    // value-splitting butterfly -> lane l holds col (l & 15)
    unsigned full = 0xffffffff;
    int b0 = lane & 1, b1i = (lane >> 1) & 1, b2 = (lane >> 2) & 1, b3 = (lane >> 3) & 1;
    float q8[8];
    #pragma unroll
    for (int j = 0; j < 8; j++) {
        float send = b0 ? p[2 * j] : p[2 * j + 1];
        float keep = b0 ? p[2 * j + 1] : p[2 * j];
        q8[j] = keep + __shfl_xor_sync(full, send, 1);
    }
    float q4[4];
    #pragma unroll
    for (int j = 0; j < 4; j++) {
        float send = b1i ? q8[2 * j] : q8[2 * j + 1];
        float keep = b1i ? q8[2 * j + 1] : q8[2 * j];
        q4[j] = keep + __shfl_xor_sync(full, send, 2);
    }
    float q2[2];
    #pragma unroll
    for (int j = 0; j < 2; j++) {
        float send = b2 ? q4[2 * j] : q4[2 * j + 1];
        float keep = b2 ? q4[2 * j + 1] : q4[2 * j];
        q2[j] = keep + __shfl_xor_sync(full, send, 4);
    }
    {
        float send = b3 ? q2[0] : q2[1];
        float keep = b3 ? q2[1] : q2[0];
        float r = keep + __shfl_xor_sync(full, send, 8);
        r += __shfl_xor_sync(full, r, 16);
        if (lane < 16)
            g_hs2[(long)n * DOUT + lane] = r * dvn;
    }
}

// ---------------------------------------------------------------------------
// agg2: 8-lane group per node, per-group shuffle masks (groups diverge).
__global__ __launch_bounds__(256) void k_agg2(const float* __restrict__ b2,
                                              float* __restrict__ out) {
    int grp  = (blockIdx.x * 256 + threadIdx.x) >> 3;
    int gl   = threadIdx.x & 7;
    unsigned gmask = 0xFFu << (threadIdx.x & 24);
    if (grp >= NN) return;
    int n   = grp;
    int off = g_offx[n];
    int cnt = g_cnt[n];

    const float2* hs = (const float2*)g_hs2;
    float2 acc = hs[(long)n * 8 + gl];

    for (int base = 0; base < cnt; base += 8) {
        int idx = base + gl;
        int e   = (idx < cnt) ? g_esrc[off + idx] : 0;
        int m   = min(8, cnt - base);
        for (int j = 0; j < m; j++) {
            int s = __shfl_sync(gmask, e, j, 8);
            float2 v = hs[(long)s * 8 + gl];
            acc.x += v.x;
            acc.y += v.y;
        }
    }

    float dv = g_dinv[n];
    float2 b = ((const float2*)b2)[gl];
    float vx = dv * acc.x + b.x;
    float vy = dv * acc.y + b.y;

    float m = fmaxf(vx, vy);
    #pragma unroll
    for (int d = 4; d >= 1; d >>= 1)
        m = fmaxf(m, __shfl_xor_sync(gmask, m, d, 8));
    float s = expf(vx - m) + expf(vy - m);
    #pragma unroll
    for (int d = 4; d >= 1; d >>= 1)
        s += __shfl_xor_sync(gmask, s, d, 8);
    float ls = m + logf(s);

    ((float2*)out)[(long)n * 8 + gl] = make_float2(vx - ls, vy - ls);
}

// ---------------------------------------------------------------------------
extern "C" void kernel_launch(void* const* d_in, const int* in_sizes, int n_in,
                              void* d_out, int out_size) {
    const float* x  = (const float*)d_in[0];
    const int*   ei = (const int*)  d_in[1];
    const float* W1 = (const float*)d_in[2];
    const float* b1 = (const float*)d_in[3];
    const float* W2 = (const float*)d_in[4];
    const float* b2 = (const float*)d_in[5];
    const int* src = ei;
    const int* dst = ei + EE;

    static cudaStream_t s2 = nullptr;
    static cudaEvent_t  e0 = nullptr, e1 = nullptr;
    if (!s2) {
        cudaStreamCreate(&s2);
        cudaEventCreateWithFlags(&e0, cudaEventDisableTiming);
        cudaEventCreateWithFlags(&e1, cudaEventDisableTiming);
        cudaFuncSetAttribute(k_gemm1, cudaFuncAttributeMaxDynamicSharedMemorySize,
                             GEMM1_SMEM);
    }

    // Fork: CSR build on s2, concurrent with gemm1 on the main stream.
    cudaEventRecord(e0, 0);
    cudaStreamWaitEvent(s2, e0, 0);

    k_zero  <<<(NN + 255) / 256, 256, 0, s2>>>();
    k_count <<<(EE + 255) / 256, 256, 0, s2>>>(dst);
    k_scanL <<<NB1, 1024, 0, s2>>>();
    k_fill  <<<(EE + 255) / 256, 256, 0, s2>>>(src, dst);
    cudaEventRecord(e1, s2);

    k_gemm1 <<<(NN + 255) / 256, 256, GEMM1_SMEM>>>(x, W1);

    // Join: agg1f needs both gemm1 (main) and CSR (s2).
    cudaStreamWaitEvent(0, e1, 0);

    k_agg1f <<<(NN * 32 + 255) / 256, 256>>>(b1, W2);
    k_agg2  <<<(NN * 8 + 255) / 256, 256>>>(b2, (float*)d_out);
}

// round 10
// speedup vs baseline: 1.0248x; 1.0076x over previous
#include <cuda_runtime.h>
#include <cuda_fp16.h>

#define NN   100000
#define EE   1600000
#define DIN  128
#define DHID 64
#define DOUT 16
#define NB1  ((NN + 1023) / 1024)   // 98 scan blocks

// Scratch (__device__ globals; allocation-free rule). All buffers are either
// rewritten fully each call or restored to their initial (zero) state by the
// end of each call -> deterministic across graph replays.
__device__ float g_dinv[NN];
__device__ __align__(16) __half g_hs1h[NN * DHID];   // raw xW1, fp16
__device__ float g_hs2[NN * DOUT];
__device__ int   g_cnt[NN];        // zero at call entry; re-zeroed by k_agg2
__device__ int   g_offx[NN];
__device__ int   g_cur[NN];
__device__ int   g_esrc[EE];
__device__ unsigned long long g_state[NB1];   // zeroed by k_count block 0

__device__ __forceinline__ unsigned h2u(__half2 h) {
    return *reinterpret_cast<unsigned*>(&h);
}

// ---------------------------------------------------------------------------
__global__ void k_count(const int* __restrict__ dst) {
    if (blockIdx.x == 0 && threadIdx.x < NB1) g_state[threadIdx.x] = 0ULL;
    int e = blockIdx.x * blockDim.x + threadIdx.x;
    if (e < EE) atomicAdd(&g_cnt[dst[e]], 1);
}

// Single-pass scan, warp-parallel decoupled lookback.
__global__ __launch_bounds__(1024) void k_scanL() {
    __shared__ int ws[32];
    __shared__ int s_excl;
    int bid = blockIdx.x;
    int i = bid * 1024 + threadIdx.x;
    int lane = threadIdx.x & 31, wid = threadIdx.x >> 5;
    const unsigned full = 0xffffffffu;

    int v = (i < NN) ? g_cnt[i] : 0;
    int s = v;
    #pragma unroll
    for (int d = 1; d < 32; d <<= 1) {
        int t = __shfl_up_sync(full, s, d);
        if (lane >= d) s += t;
    }
    if (lane == 31) ws[wid] = s;
    __syncthreads();
    if (wid == 0) {
        int w = ws[lane];
        #pragma unroll
        for (int d = 1; d < 32; d <<= 1) {
            int t = __shfl_up_sync(full, w, d);
            if (lane >= d) w += t;
        }
        ws[lane] = w;
    }
    __syncthreads();

    if (wid == 0) {
        int total = ws[31];
        if (bid == 0) {
            if (lane == 0) {
                atomicExch(&g_state[0], (2ULL << 32) | (unsigned)total);
                s_excl = 0;
            }
        } else {
            if (lane == 0)
                atomicExch(&g_state[bid], (1ULL << 32) | (unsigned)total);
            int excl = 0;
            int p = bid - 1;
            while (true) {
                int idx = p - lane;
                unsigned long long st = (idx >= 0)
                    ? atomicAdd(&g_state[idx], 0ULL)
                    : (2ULL << 32);
                unsigned flag = (unsigned)(st >> 32);
                int      val  = (int)(unsigned)st;
                unsigned zero_mask = __ballot_sync(full, flag == 0);
                unsigned pref_mask = __ballot_sync(full, flag == 2);
                int firstPref = pref_mask ? (__ffs(pref_mask) - 1) : 32;
                unsigned before = (firstPref >= 32) ? full
                                                    : ((firstPref == 31) ? 0x7fffffffu
                                                                         : ((1u << firstPref) - 1));
                if (zero_mask & before) continue;
                if (firstPref < 32) {
                    int contrib = (lane <= firstPref) ? val : 0;
                    #pragma unroll
                    for (int d = 16; d >= 1; d >>= 1)
                        contrib += __shfl_xor_sync(full, contrib, d);
                    excl += contrib;
                    break;
                } else {
                    if (zero_mask) continue;
                    int contrib = (idx >= 0) ? val : 0;
                    #pragma unroll
                    for (int d = 16; d >= 1; d >>= 1)
                        contrib += __shfl_xor_sync(full, contrib, d);
                    excl += contrib;
                    p -= 32;
                }
            }
            if (lane == 0) {
                atomicExch(&g_state[bid], (2ULL << 32) | (unsigned)(excl + total));
                s_excl = excl;
            }
        }
    }
    __syncthreads();

    if (i < NN) {
        int inclB = s + (wid > 0 ? ws[wid - 1] : 0);
        int excl  = s_excl + inclB - v;
        g_offx[i] = excl;
        g_cur[i]  = excl;
        g_dinv[i] = rsqrtf((float)(v + 1));
    }
}

__global__ void k_fill(const int* __restrict__ src, const int* __restrict__ dst) {
    int e = blockIdx.x * blockDim.x + threadIdx.x;
    if (e >= EE) return;
    int d = dst[e];
    int p = atomicAdd(&g_cur[d], 1);
    g_esrc[p] = src[e];
}

// ---------------------------------------------------------------------------
// GEMM1 on tensor cores (fp16 HMMA, fp32 accum): hs1h = x @ W1.
#define XS_STRIDE 136
#define WS_STRIDE 72
#define GEMM1_SMEM ((256 * XS_STRIDE + DIN * WS_STRIDE) * 2)

__device__ __forceinline__ void ldsm_x4(unsigned* d, unsigned addr) {
    asm volatile("ldmatrix.sync.aligned.m8n8.x4.shared.b16 {%0,%1,%2,%3}, [%4];"
        : "=r"(d[0]), "=r"(d[1]), "=r"(d[2]), "=r"(d[3]) : "r"(addr));
}
__device__ __forceinline__ void ldsm_x4_t(unsigned* d, unsigned addr) {
    asm volatile("ldmatrix.sync.aligned.m8n8.x4.trans.shared.b16 {%0,%1,%2,%3}, [%4];"
        : "=r"(d[0]), "=r"(d[1]), "=r"(d[2]), "=r"(d[3]) : "r"(addr));
}
__device__ __forceinline__ void mma16816(float* c, const unsigned* a,
                                         unsigned b0, unsigned b1) {
    asm volatile("mma.sync.aligned.m16n8k16.row.col.f32.f16.f16.f32 "
        "{%0,%1,%2,%3}, {%4,%5,%6,%7}, {%8,%9}, {%0,%1,%2,%3};"
        : "+f"(c[0]), "+f"(c[1]), "+f"(c[2]), "+f"(c[3])
        : "r"(a[0]), "r"(a[1]), "r"(a[2]), "r"(a[3]), "r"(b0), "r"(b1));
}

__global__ __launch_bounds__(256) void k_gemm1(const float* __restrict__ x,
                                               const float* __restrict__ W1) {
    extern __shared__ __half sm[];
    __half* xs = sm;
    __half* ws = sm + 256 * XS_STRIDE;
    int tid = threadIdx.x;
    int rowBase = blockIdx.x * 256;

    for (int i = tid; i < DIN * DHID; i += 256) {
        int k = i >> 6, n = i & 63;
        ws[k * WS_STRIDE + n] = __float2half(W1[i]);
    }
    const float4* x4 = (const float4*)x;
    #pragma unroll
    for (int it = 0; it < 32; it++) {
        int f   = tid + it * 256;
        int row = f >> 5, c4 = f & 31;
        if (rowBase + row < NN) {
            float4 v = x4[(long)(rowBase + row) * 32 + c4];
            uint2 u;
            u.x = h2u(__floats2half2_rn(v.x, v.y));
            u.y = h2u(__floats2half2_rn(v.z, v.w));
            *reinterpret_cast<uint2*>(&xs[row * XS_STRIDE + c4 * 4]) = u;
        }
    }
    __syncthreads();

    int warp = tid >> 5, lane = tid & 31;
    int g = lane >> 3, r = lane & 7;

    float c[2][8][4];
    #pragma unroll
    for (int mt = 0; mt < 2; mt++)
        #pragma unroll
        for (int nt = 0; nt < 8; nt++)
            #pragma unroll
            for (int q = 0; q < 4; q++) c[mt][nt][q] = 0.f;

    unsigned xs_base = (unsigned)__cvta_generic_to_shared(xs);
    unsigned ws_base = (unsigned)__cvta_generic_to_shared(ws);

    #pragma unroll
    for (int kk = 0; kk < 8; kk++) {
        unsigned a[2][4];
        #pragma unroll
        for (int mt = 0; mt < 2; mt++) {
            int m = warp * 32 + mt * 16 + (g & 1) * 8 + r;
            unsigned addr = xs_base + (m * XS_STRIDE + kk * 16 + (g >> 1) * 8) * 2;
            ldsm_x4(a[mt], addr);
        }
        #pragma unroll
        for (int np = 0; np < 4; np++) {
            int k = kk * 16 + (g & 1) * 8 + r;
            int n = np * 16 + (g >> 1) * 8;
            unsigned addr = ws_base + (k * WS_STRIDE + n) * 2;
            unsigned b[4];
            ldsm_x4_t(b, addr);
            mma16816(c[0][np * 2 + 0], a[0], b[0], b[1]);
            mma16816(c[0][np * 2 + 1], a[0], b[2], b[3]);
            mma16816(c[1][np * 2 + 0], a[1], b[0], b[1]);
            mma16816(c[1][np * 2 + 1], a[1], b[2], b[3]);
        }
    }

    int rq = lane >> 2, cq = (lane & 3) * 2;
    #pragma unroll
    for (int mt = 0; mt < 2; mt++) {
        int row0 = rowBase + warp * 32 + mt * 16 + rq;
        #pragma unroll
        for (int nt = 0; nt < 8; nt++) {
            int col = nt * 8 + cq;
            if (row0 < NN)
                *reinterpret_cast<__half2*>(g_hs1h + (long)row0 * DHID + col) =
                    __floats2half2_rn(c[mt][nt][0], c[mt][nt][1]);
            if (row0 + 8 < NN)
                *reinterpret_cast<__half2*>(g_hs1h + (long)(row0 + 8) * DHID + col) =
                    __floats2half2_rn(c[mt][nt][2], c[mt][nt][3]);
        }
    }
}

// ---------------------------------------------------------------------------
// Fused agg1 + gemm2: one warp per node. Edge loop batched 4-wide for MLP.
__global__ __launch_bounds__(256) void k_agg1f(const float* __restrict__ b1,
                                               const float* __restrict__ W2) {
    __shared__ float sW2t[DOUT * DHID];   // [c][k], 4 KB
    int tid = threadIdx.x;
    for (int i = tid; i < DOUT * DHID; i += 256) {
        int c = i >> 6, k = i & 63;
        sW2t[i] = W2[k * DOUT + c];
    }
    __syncthreads();

    int n    = (blockIdx.x * 256 + tid) >> 5;
    int lane = tid & 31;
    if (n >= NN) return;
    int off = g_offx[n];
    int cnt = g_cnt[n];
    float dvn = g_dinv[n];
    const unsigned full = 0xffffffffu;

    const __half2* hs = (const __half2*)g_hs1h;
    float2 self = __half22float2(hs[(long)n * 32 + lane]);
    float2 acc;
    acc.x = self.x * dvn;
    acc.y = self.y * dvn;

    for (int base = 0; base < cnt; base += 32) {
        int idx = base + lane;
        int   e  = 0;
        float ds = 0.f;
        if (idx < cnt) {
            e  = g_esrc[off + idx];
            ds = g_dinv[e];
        }
        int m = min(32, cnt - base);
        int j = 0;
        for (; j + 4 <= m; j += 4) {      // 4 independent row loads in flight
            int s0 = __shfl_sync(full, e, j);
            int s1 = __shfl_sync(full, e, j + 1);
            int s2 = __shfl_sync(full, e, j + 2);
            int s3 = __shfl_sync(full, e, j + 3);
            float d0 = __shfl_sync(full, ds, j);
            float d1 = __shfl_sync(full, ds, j + 1);
            float d2 = __shfl_sync(full, ds, j + 2);
            float d3 = __shfl_sync(full, ds, j + 3);
            float2 v0 = __half22float2(hs[(long)s0 * 32 + lane]);
            float2 v1 = __half22float2(hs[(long)s1 * 32 + lane]);
            float2 v2 = __half22float2(hs[(long)s2 * 32 + lane]);
            float2 v3 = __half22float2(hs[(long)s3 * 32 + lane]);
            acc.x = fmaf(v0.x, d0, fmaf(v1.x, d1, fmaf(v2.x, d2, fmaf(v3.x, d3, acc.x))));
            acc.y = fmaf(v0.y, d0, fmaf(v1.y, d1, fmaf(v2.y, d2, fmaf(v3.y, d3, acc.y))));
        }
        for (; j < m; j++) {
            int   s  = __shfl_sync(full, e, j);
            float dj = __shfl_sync(full, ds, j);
            float2 v = __half22float2(hs[(long)s * 32 + lane]);
            acc.x = fmaf(v.x, dj, acc.x);
            acc.y = fmaf(v.y, dj, acc.y);
        }
    }

    float2 b = ((const float2*)b1)[lane];
    float x0 = fmaxf(dvn * acc.x + b.x, 0.f);
    float x1 = fmaxf(dvn * acc.y + b.y, 0.f);

    float p[16];
    #pragma unroll
    for (int c = 0; c < 16; c++) {
        float2 w = ((const float2*)&sW2t[c * DHID])[lane];
        p[c] = x0 * w.x + x1 * w.y;
    }

    // value-splitting butterfly -> lane l holds col (l & 15)
    int b0 = lane & 1, b1i = (lane >> 1) & 1, b2 = (lane >> 2) & 1, b3 = (lane >> 3) & 1;
    float q8[8];
    #pragma unroll
    for (int j = 0; j < 8; j++) {
        float send = b0 ? p[2 * j] : p[2 * j + 1];
        float keep = b0 ? p[2 * j + 1] : p[2 * j];
        q8[j] = keep + __shfl_xor_sync(full, send, 1);
    }
    float q4[4];
    #pragma unroll
    for (int j = 0; j < 4; j++) {
        float send = b1i ? q8[2 * j] : q8[2 * j + 1];
        float keep = b1i ? q8[2 * j + 1] : q8[2 * j];
        q4[j] = keep + __shfl_xor_sync(full, send, 2);
    }
    float q2[2];
    #pragma unroll
    for (int j = 0; j < 2; j++) {
        float send = b2 ? q4[2 * j] : q4[2 * j + 1];
        float keep = b2 ? q4[2 * j + 1] : q4[2 * j];
        q2[j] = keep + __shfl_xor_sync(full, send, 4);
    }
    {
        float send = b3 ? q2[0] : q2[1];
        float keep = b3 ? q2[1] : q2[0];
        float r = keep + __shfl_xor_sync(full, send, 8);
        r += __shfl_xor_sync(full, r, 16);
        if (lane < 16)
            g_hs2[(long)n * DOUT + lane] = r * dvn;
    }
}

// ---------------------------------------------------------------------------
// agg2: 8-lane group per node; MLP-2 edge loop; re-zeroes g_cnt for next call.
__global__ __launch_bounds__(256) void k_agg2(const float* __restrict__ b2,
                                              float* __restrict__ out) {
    int grp  = (blockIdx.x * 256 + threadIdx.x) >> 3;
    int gl   = threadIdx.x & 7;
    unsigned gmask = 0xFFu << (threadIdx.x & 24);
    if (grp >= NN) return;
    int n   = grp;
    int off = g_offx[n];
    int cnt = g_cnt[n];
    if (gl == 0) g_cnt[n] = 0;          // restore invariant for next call

    const float2* hs = (const float2*)g_hs2;
    float2 acc = hs[(long)n * 8 + gl];

    for (int base = 0; base < cnt; base += 8) {
        int idx = base + gl;
        int e   = (idx < cnt) ? g_esrc[off + idx] : 0;
        int m   = min(8, cnt - base);
        int j = 0;
        for (; j + 2 <= m; j += 2) {
            int s0 = __shfl_sync(gmask, e, j, 8);
            int s1 = __shfl_sync(gmask, e, j + 1, 8);
            float2 v0 = hs[(long)s0 * 8 + gl];
            float2 v1 = hs[(long)s1 * 8 + gl];
            acc.x += v0.x + v1.x;
            acc.y += v0.y + v1.y;
        }
        for (; j < m; j++) {
            int s = __shfl_sync(gmask, e, j, 8);
            float2 v = hs[(long)s * 8 + gl];
            acc.x += v.x;
            acc.y += v.y;
        }
    }

    float dv = g_dinv[n];
    float2 b = ((const float2*)b2)[gl];
    float vx = dv * acc.x + b.x;
    float vy = dv * acc.y + b.y;

    float m = fmaxf(vx, vy);
    #pragma unroll
    for (int d = 4; d >= 1; d >>= 1)
        m = fmaxf(m, __shfl_xor_sync(gmask, m, d, 8));
    float s = expf(vx - m) + expf(vy - m);
    #pragma unroll
    for (int d = 4; d >= 1; d >>= 1)
        s += __shfl_xor_sync(gmask, s, d, 8);
    float ls = m + logf(s);

    ((float2*)out)[(long)n * 8 + gl] = make_float2(vx - ls, vy - ls);
}

// ---------------------------------------------------------------------------
extern "C" void kernel_launch(void* const* d_in, const int* in_sizes, int n_in,
                              void* d_out, int out_size) {
    const float* x  = (const float*)d_in[0];
    const int*   ei = (const int*)  d_in[1];
    const float* W1 = (const float*)d_in[2];
    const float* b1 = (const float*)d_in[3];
    const float* W2 = (const float*)d_in[4];
    const float* b2 = (const float*)d_in[5];
    const int* src = ei;
    const int* dst = ei + EE;

    static cudaStream_t s2 = nullptr;
    static cudaEvent_t  e0 = nullptr, e1 = nullptr;
    if (!s2) {
        cudaStreamCreate(&s2);
        cudaEventCreateWithFlags(&e0, cudaEventDisableTiming);
        cudaEventCreateWithFlags(&e1, cudaEventDisableTiming);
        cudaFuncSetAttribute(k_gemm1, cudaFuncAttributeMaxDynamicSharedMemorySize,
                             GEMM1_SMEM);
    }

    // Fork: CSR build on s2, concurrent with gemm1 on the main stream.
    cudaEventRecord(e0, 0);
    cudaStreamWaitEvent(s2, e0, 0);

    k_count <<<(EE + 255) / 256, 256, 0, s2>>>(dst);
    k_scanL <<<NB1, 1024, 0, s2>>>();
    k_fill  <<<(EE + 255) / 256, 256, 0, s2>>>(src, dst);
    cudaEventRecord(e1, s2);

    k_gemm1 <<<(NN + 255) / 256, 256, GEMM1_SMEM>>>(x, W1);

    // Join: agg1f needs both gemm1 (main) and CSR (s2).
    cudaStreamWaitEvent(0, e1, 0);

    k_agg1f <<<(NN * 32 + 255) / 256, 256>>>(b1, W2);
    k_agg2  <<<(NN * 8 + 255) / 256, 256>>>(b2, (float*)d_out);
}

// round 11
// speedup vs baseline: 1.1179x; 1.0908x over previous
#include <cuda_runtime.h>
#include <cuda_fp16.h>

#define NN   100000
#define EE   1600000
#define DIN  128
#define DHID 64
#define DOUT 16
#define NB1  ((NN + 1023) / 1024)   // 98 scan blocks

// Scratch (__device__ globals; allocation-free rule). Every buffer is either
// fully rewritten each call or restored to zero by end-of-call -> deterministic.
__device__ float g_dinv[NN];
__device__ __align__(16) __half g_hs1h[NN * DHID];   // raw xW1, fp16
__device__ __align__(16) __half g_x1h[NN * DHID];    // relu(layer1), fp16
__device__ float g_hs2[NN * DOUT];
__device__ int   g_cnt[NN];        // zero at entry; re-zeroed by k_agg2
__device__ int   g_offx[NN];
__device__ int   g_cur[NN];
__device__ int   g_esrc[EE];
__device__ unsigned long long g_state[NB1];   // zeroed by k_count block 0

__device__ __forceinline__ unsigned h2u(__half2 h) {
    return *reinterpret_cast<unsigned*>(&h);
}

// ---------------------------------------------------------------------------
__global__ void k_count(const int* __restrict__ dst) {
    if (blockIdx.x == 0 && threadIdx.x < NB1) g_state[threadIdx.x] = 0ULL;
    int q = blockIdx.x * blockDim.x + threadIdx.x;     // int4 index
    if (q < EE / 4) {
        int4 d = ((const int4*)dst)[q];
        atomicAdd(&g_cnt[d.x], 1);
        atomicAdd(&g_cnt[d.y], 1);
        atomicAdd(&g_cnt[d.z], 1);
        atomicAdd(&g_cnt[d.w], 1);
    }
}

// Single-pass scan, warp-parallel decoupled lookback.
__global__ __launch_bounds__(1024) void k_scanL() {
    __shared__ int ws[32];
    __shared__ int s_excl;
    int bid = blockIdx.x;
    int i = bid * 1024 + threadIdx.x;
    int lane = threadIdx.x & 31, wid = threadIdx.x >> 5;
    const unsigned full = 0xffffffffu;

    int v = (i < NN) ? g_cnt[i] : 0;
    int s = v;
    #pragma unroll
    for (int d = 1; d < 32; d <<= 1) {
        int t = __shfl_up_sync(full, s, d);
        if (lane >= d) s += t;
    }
    if (lane == 31) ws[wid] = s;
    __syncthreads();
    if (wid == 0) {
        int w = ws[lane];
        #pragma unroll
        for (int d = 1; d < 32; d <<= 1) {
            int t = __shfl_up_sync(full, w, d);
            if (lane >= d) w += t;
        }
        ws[lane] = w;
    }
    __syncthreads();

    if (wid == 0) {
        int total = ws[31];
        if (bid == 0) {
            if (lane == 0) {
                atomicExch(&g_state[0], (2ULL << 32) | (unsigned)total);
                s_excl = 0;
            }
        } else {
            if (lane == 0)
                atomicExch(&g_state[bid], (1ULL << 32) | (unsigned)total);
            int excl = 0;
            int p = bid - 1;
            while (true) {
                int idx = p - lane;
                unsigned long long st = (idx >= 0)
                    ? atomicAdd(&g_state[idx], 0ULL)
                    : (2ULL << 32);
                unsigned flag = (unsigned)(st >> 32);
                int      val  = (int)(unsigned)st;
                unsigned zero_mask = __ballot_sync(full, flag == 0);
                unsigned pref_mask = __ballot_sync(full, flag == 2);
                int firstPref = pref_mask ? (__ffs(pref_mask) - 1) : 32;
                unsigned before = (firstPref >= 32) ? full
                                                    : ((firstPref == 31) ? 0x7fffffffu
                                                                         : ((1u << firstPref) - 1));
                if (zero_mask & before) continue;
                if (firstPref < 32) {
                    int contrib = (lane <= firstPref) ? val : 0;
                    #pragma unroll
                    for (int d = 16; d >= 1; d >>= 1)
                        contrib += __shfl_xor_sync(full, contrib, d);
                    excl += contrib;
                    break;
                } else {
                    if (zero_mask) continue;
                    int contrib = (idx >= 0) ? val : 0;
                    #pragma unroll
                    for (int d = 16; d >= 1; d >>= 1)
                        contrib += __shfl_xor_sync(full, contrib, d);
                    excl += contrib;
                    p -= 32;
                }
            }
            if (lane == 0) {
                atomicExch(&g_state[bid], (2ULL << 32) | (unsigned)(excl + total));
                s_excl = excl;
            }
        }
    }
    __syncthreads();

    if (i < NN) {
        int inclB = s + (wid > 0 ? ws[wid - 1] : 0);
        int excl  = s_excl + inclB - v;
        g_offx[i] = excl;
        g_cur[i]  = excl;
        g_dinv[i] = rsqrtf((float)(v + 1));
    }
}

__global__ void k_fill(const int* __restrict__ src, const int* __restrict__ dst) {
    int e = blockIdx.x * blockDim.x + threadIdx.x;
    if (e >= EE) return;
    int d = dst[e];
    int p = atomicAdd(&g_cur[d], 1);
    g_esrc[p] = src[e];
}

// ---------------------------------------------------------------------------
// GEMM1 on tensor cores (fp16 HMMA, fp32 accum): hs1h = x @ W1.
#define XS_STRIDE 136
#define WS_STRIDE 72
#define GEMM1_SMEM ((256 * XS_STRIDE + DIN * WS_STRIDE) * 2)

__device__ __forceinline__ void ldsm_x4(unsigned* d, unsigned addr) {
    asm volatile("ldmatrix.sync.aligned.m8n8.x4.shared.b16 {%0,%1,%2,%3}, [%4];"
        : "=r"(d[0]), "=r"(d[1]), "=r"(d[2]), "=r"(d[3]) : "r"(addr));
}
__device__ __forceinline__ void ldsm_x4_t(unsigned* d, unsigned addr) {
    asm volatile("ldmatrix.sync.aligned.m8n8.x4.trans.shared.b16 {%0,%1,%2,%3}, [%4];"
        : "=r"(d[0]), "=r"(d[1]), "=r"(d[2]), "=r"(d[3]) : "r"(addr));
}
__device__ __forceinline__ void mma16816(float* c, const unsigned* a,
                                         unsigned b0, unsigned b1) {
    asm volatile("mma.sync.aligned.m16n8k16.row.col.f32.f16.f16.f32 "
        "{%0,%1,%2,%3}, {%4,%5,%6,%7}, {%8,%9}, {%0,%1,%2,%3};"
        : "+f"(c[0]), "+f"(c[1]), "+f"(c[2]), "+f"(c[3])
        : "r"(a[0]), "r"(a[1]), "r"(a[2]), "r"(a[3]), "r"(b0), "r"(b1));
}

__global__ __launch_bounds__(256) void k_gemm1(const float* __restrict__ x,
                                               const float* __restrict__ W1) {
    extern __shared__ __half sm[];
    __half* xs = sm;
    __half* ws = sm + 256 * XS_STRIDE;
    int tid = threadIdx.x;
    int rowBase = blockIdx.x * 256;

    for (int i = tid; i < DIN * DHID; i += 256) {
        int k = i >> 6, n = i & 63;
        ws[k * WS_STRIDE + n] = __float2half(W1[i]);
    }
    const float4* x4 = (const float4*)x;
    #pragma unroll
    for (int it = 0; it < 32; it++) {
        int f   = tid + it * 256;
        int row = f >> 5, c4 = f & 31;
        if (rowBase + row < NN) {
            float4 v = x4[(long)(rowBase + row) * 32 + c4];
            uint2 u;
            u.x = h2u(__floats2half2_rn(v.x, v.y));
            u.y = h2u(__floats2half2_rn(v.z, v.w));
            *reinterpret_cast<uint2*>(&xs[row * XS_STRIDE + c4 * 4]) = u;
        }
    }
    __syncthreads();

    int warp = tid >> 5, lane = tid & 31;
    int g = lane >> 3, r = lane & 7;

    float c[2][8][4];
    #pragma unroll
    for (int mt = 0; mt < 2; mt++)
        #pragma unroll
        for (int nt = 0; nt < 8; nt++)
            #pragma unroll
            for (int q = 0; q < 4; q++) c[mt][nt][q] = 0.f;

    unsigned xs_base = (unsigned)__cvta_generic_to_shared(xs);
    unsigned ws_base = (unsigned)__cvta_generic_to_shared(ws);

    #pragma unroll
    for (int kk = 0; kk < 8; kk++) {
        unsigned a[2][4];
        #pragma unroll
        for (int mt = 0; mt < 2; mt++) {
            int m = warp * 32 + mt * 16 + (g & 1) * 8 + r;
            unsigned addr = xs_base + (m * XS_STRIDE + kk * 16 + (g >> 1) * 8) * 2;
            ldsm_x4(a[mt], addr);
        }
        #pragma unroll
        for (int np = 0; np < 4; np++) {
            int k = kk * 16 + (g & 1) * 8 + r;
            int n = np * 16 + (g >> 1) * 8;
            unsigned addr = ws_base + (k * WS_STRIDE + n) * 2;
            unsigned b[4];
            ldsm_x4_t(b, addr);
            mma16816(c[0][np * 2 + 0], a[0], b[0], b[1]);
            mma16816(c[0][np * 2 + 1], a[0], b[2], b[3]);
            mma16816(c[1][np * 2 + 0], a[1], b[0], b[1]);
            mma16816(c[1][np * 2 + 1], a[1], b[2], b[3]);
        }
    }

    int rq = lane >> 2, cq = (lane & 3) * 2;
    #pragma unroll
    for (int mt = 0; mt < 2; mt++) {
        int row0 = rowBase + warp * 32 + mt * 16 + rq;
        #pragma unroll
        for (int nt = 0; nt < 8; nt++) {
            int col = nt * 8 + cq;
            if (row0 < NN)
                *reinterpret_cast<__half2*>(g_hs1h + (long)row0 * DHID + col) =
                    __floats2half2_rn(c[mt][nt][0], c[mt][nt][1]);
            if (row0 + 8 < NN)
                *reinterpret_cast<__half2*>(g_hs1h + (long)(row0 + 8) * DHID + col) =
                    __floats2half2_rn(c[mt][nt][2], c[mt][nt][3]);
        }
    }
}

// ---------------------------------------------------------------------------
// agg1: one warp per node; lane owns half2 (2 feats); MLP-4 edge loop.
// x1h[n] = relu(dinv[n]*(sum_s dinv[s]*hs[s] + dinv[n]*hs[n]) + b1)
__global__ __launch_bounds__(256) void k_agg1(const float* __restrict__ b1) {
    int n    = (blockIdx.x * 256 + threadIdx.x) >> 5;
    int lane = threadIdx.x & 31;
    if (n >= NN) return;
    int off = g_offx[n];
    int cnt = g_cnt[n];
    float dvn = g_dinv[n];
    const unsigned full = 0xffffffffu;

    const __half2* hs = (const __half2*)g_hs1h;
    float2 self = __half22float2(hs[(long)n * 32 + lane]);
    float2 acc;
    acc.x = self.x * dvn;
    acc.y = self.y * dvn;

    for (int base = 0; base < cnt; base += 32) {
        int idx = base + lane;
        int   e  = 0;
        float ds = 0.f;
        if (idx < cnt) {
            e  = g_esrc[off + idx];
            ds = g_dinv[e];
        }
        int m = min(32, cnt - base);
        int j = 0;
        for (; j + 4 <= m; j += 4) {
            int s0 = __shfl_sync(full, e, j);
            int s1 = __shfl_sync(full, e, j + 1);
            int s2 = __shfl_sync(full, e, j + 2);
            int s3 = __shfl_sync(full, e, j + 3);
            float d0 = __shfl_sync(full, ds, j);
            float d1 = __shfl_sync(full, ds, j + 1);
            float d2 = __shfl_sync(full, ds, j + 2);
            float d3 = __shfl_sync(full, ds, j + 3);
            float2 v0 = __half22float2(hs[(long)s0 * 32 + lane]);
            float2 v1 = __half22float2(hs[(long)s1 * 32 + lane]);
            float2 v2 = __half22float2(hs[(long)s2 * 32 + lane]);
            float2 v3 = __half22float2(hs[(long)s3 * 32 + lane]);
            acc.x = fmaf(v0.x, d0, fmaf(v1.x, d1, fmaf(v2.x, d2, fmaf(v3.x, d3, acc.x))));
            acc.y = fmaf(v0.y, d0, fmaf(v1.y, d1, fmaf(v2.y, d2, fmaf(v3.y, d3, acc.y))));
        }
        for (; j < m; j++) {
            int   s  = __shfl_sync(full, e, j);
            float dj = __shfl_sync(full, ds, j);
            float2 v = __half22float2(hs[(long)s * 32 + lane]);
            acc.x = fmaf(v.x, dj, acc.x);
            acc.y = fmaf(v.y, dj, acc.y);
        }
    }

    float2 b = ((const float2*)b1)[lane];
    float o0 = fmaxf(dvn * acc.x + b.x, 0.f);
    float o1 = fmaxf(dvn * acc.y + b.y, 0.f);
    ((__half2*)g_x1h)[(long)n * 32 + lane] = __floats2half2_rn(o0, o1);
}

// ---------------------------------------------------------------------------
// GEMM2: hs2 = (x1h @ W2) * dinv. 128 thr -> 256x16 tile, 8x4/thr.
#define KC 32
__global__ __launch_bounds__(128) void k_gemm2(const float* __restrict__ W2) {
    __shared__ float sW[DHID * DOUT];
    __shared__ float xs[256][KC + 1];

    int tid = threadIdx.x;
    int tx  = tid & 3;
    int ty  = tid >> 2;
    int rowBase = blockIdx.x * 256;

    {
        const float4* W4 = (const float4*)W2;
        float4* sW4 = (float4*)sW;
        #pragma unroll
        for (int i = 0; i < DHID * DOUT / 4 / 128; i++)
            sW4[tid + i * 128] = W4[tid + i * 128];
    }

    float acc[8][4];
    #pragma unroll
    for (int r = 0; r < 8; r++)
        #pragma unroll
        for (int c = 0; c < 4; c++) acc[r][c] = 0.f;

    const __half2* x1h2 = (const __half2*)g_x1h;
    for (int kc = 0; kc < DHID; kc += KC) {
        __syncthreads();
        // stage 256 rows x 32 cols (16 half2 per row) -> fp32 smem
        #pragma unroll
        for (int it = 0; it < 32; it++) {
            int f   = tid + it * 128;          // half2 slot id in [0,4096)
            int row = f >> 4;
            int h2  = f & 15;                  // which half2 within the chunk
            float2 v = make_float2(0.f, 0.f);
            if (rowBase + row < NN)
                v = __half22float2(x1h2[(long)(rowBase + row) * 32 + (kc >> 1) + h2]);
            xs[row][h2 * 2 + 0] = v.x;
            xs[row][h2 * 2 + 1] = v.y;
        }
        __syncthreads();

        #pragma unroll
        for (int k = 0; k < KC; k++) {
            float4 w = *(const float4*)&sW[(kc + k) * DOUT + tx * 4];
            #pragma unroll
            for (int r = 0; r < 8; r++) {
                float xv = xs[ty * 8 + r][k];
                acc[r][0] += xv * w.x; acc[r][1] += xv * w.y;
                acc[r][2] += xv * w.z; acc[r][3] += xv * w.w;
            }
        }
    }

    #pragma unroll
    for (int r = 0; r < 8; r++) {
        int row = rowBase + ty * 8 + r;
        if (row < NN) {
            float dv = g_dinv[row];
            ((float4*)(g_hs2 + (long)row * DOUT))[tx] =
                make_float4(acc[r][0] * dv, acc[r][1] * dv, acc[r][2] * dv, acc[r][3] * dv);
        }
    }
}

// ---------------------------------------------------------------------------
// agg2: 8-lane group per node; per-group masks; re-zeroes g_cnt for next call.
__global__ __launch_bounds__(256) void k_agg2(const float* __restrict__ b2,
                                              float* __restrict__ out) {
    int grp  = (blockIdx.x * 256 + threadIdx.x) >> 3;
    int gl   = threadIdx.x & 7;
    unsigned gmask = 0xFFu << (threadIdx.x & 24);
    if (grp >= NN) return;
    int n   = grp;
    int off = g_offx[n];
    int cnt = g_cnt[n];
    if (gl == 0) g_cnt[n] = 0;          // restore invariant for next call

    const float2* hs = (const float2*)g_hs2;
    float2 acc = hs[(long)n * 8 + gl];

    for (int base = 0; base < cnt; base += 8) {
        int idx = base + gl;
        int e   = (idx < cnt) ? g_esrc[off + idx] : 0;
        int m   = min(8, cnt - base);
        int j = 0;
        for (; j + 2 <= m; j += 2) {
            int s0 = __shfl_sync(gmask, e, j, 8);
            int s1 = __shfl_sync(gmask, e, j + 1, 8);
            float2 v0 = hs[(long)s0 * 8 + gl];
            float2 v1 = hs[(long)s1 * 8 + gl];
            acc.x += v0.x + v1.x;
            acc.y += v0.y + v1.y;
        }
        for (; j < m; j++) {
            int s = __shfl_sync(gmask, e, j, 8);
            float2 v = hs[(long)s * 8 + gl];
            acc.x += v.x;
            acc.y += v.y;
        }
    }

    float dv = g_dinv[n];
    float2 b = ((const float2*)b2)[gl];
    float vx = dv * acc.x + b.x;
    float vy = dv * acc.y + b.y;

    float m = fmaxf(vx, vy);
    #pragma unroll
    for (int d = 4; d >= 1; d >>= 1)
        m = fmaxf(m, __shfl_xor_sync(gmask, m, d, 8));
    float s = expf(vx - m) + expf(vy - m);
    #pragma unroll
    for (int d = 4; d >= 1; d >>= 1)
        s += __shfl_xor_sync(gmask, s, d, 8);
    float ls = m + logf(s);

    ((float2*)out)[(long)n * 8 + gl] = make_float2(vx - ls, vy - ls);
}

// ---------------------------------------------------------------------------
extern "C" void kernel_launch(void* const* d_in, const int* in_sizes, int n_in,
                              void* d_out, int out_size) {
    const float* x  = (const float*)d_in[0];
    const int*   ei = (const int*)  d_in[1];
    const float* W1 = (const float*)d_in[2];
    const float* b1 = (const float*)d_in[3];
    const float* W2 = (const float*)d_in[4];
    const float* b2 = (const float*)d_in[5];
    const int* src = ei;
    const int* dst = ei + EE;

    static cudaStream_t s2 = nullptr;
    static cudaEvent_t  e0 = nullptr, e1 = nullptr;
    if (!s2) {
        cudaStreamCreate(&s2);
        cudaEventCreateWithFlags(&e0, cudaEventDisableTiming);
        cudaEventCreateWithFlags(&e1, cudaEventDisableTiming);
        cudaFuncSetAttribute(k_gemm1, cudaFuncAttributeMaxDynamicSharedMemorySize,
                             GEMM1_SMEM);
    }

    // Fork: CSR build on s2, concurrent with gemm1 on the main stream.
    cudaEventRecord(e0, 0);
    cudaStreamWaitEvent(s2, e0, 0);

    k_count <<<(EE / 4 + 255) / 256, 256, 0, s2>>>(dst);
    k_scanL <<<NB1, 1024, 0, s2>>>();
    k_fill  <<<(EE + 255) / 256, 256, 0, s2>>>(src, dst);
    cudaEventRecord(e1, s2);

    k_gemm1 <<<(NN + 255) / 256, 256, GEMM1_SMEM>>>(x, W1);

    // Join: agg1 needs both gemm1 (main) and CSR (s2).
    cudaStreamWaitEvent(0, e1, 0);

    k_agg1  <<<(NN * 32 + 255) / 256, 256>>>(b1);
    k_gemm2 <<<(NN + 255) / 256, 128>>>(W2);
    k_agg2  <<<(NN * 8 + 255) / 256, 256>>>(b2, (float*)d_out);
}